// round 7
// baseline (speedup 1.0000x reference)
#include <cuda_runtime.h>

// ---------------------------------------------------------------------------
// ScalarDotProductCriticNetworkV8 — fused kernel, 2 batches per CTA (R7).
//
// Shapes: B=512, N=16, A=16, OBS=112, D=128, H=64, F_IN=128. Grid=256, NB=2.
//
// R7 vs R6 (51.4us, latency-bound: L1 47%, issue 27%, occ 21.5%):
//  * Fuse P1+P2 states pass: one stT read feeds ka+qa+sh (24 FFMA2 per
//    4 LDS.128). Saves 448 LDS.128/thread.
//  * __launch_bounds__(256,3): occ 3 (24 warps/SM) for latency hiding.
//  * Order: fused loop -> k/q store -> scores/softmax -> act/pol tails
//    (sh lives in regs across the barrier) -> av overwrites dead k/q.
// ---------------------------------------------------------------------------

#define ULL unsigned long long

#define PACK2(d, lo, hi) asm("mov.b64 %0, {%1, %2};" : "=l"(d) : "f"(lo), "f"(hi))
#define UNPACK2(lo, hi, v) asm("mov.b64 {%0, %1}, %2;" : "=f"(lo), "=f"(hi) : "l"(v))
#define FMA2(acc, a, b) asm("fma.rn.f32x2 %0, %1, %2, %0;" : "+l"(acc) : "l"(a), "l"(b))
#define TANHA(y, x) asm("tanh.approx.f32 %0, %1;" : "=f"(y) : "f"(x))

// Pre-transposed weights (scratch; filled by prep kernel each launch).
__device__ float g_WkT[112 * 128];   // [kk][c]
__device__ float g_WqT[112 * 128];   // [kk][c]
__device__ float g_WvT[128 * 128];   // [f][c]
__device__ float g_W1T[128 * 64];    // [d][h]

__global__ void prep_weights(const float* __restrict__ Wk, const float* __restrict__ Wq,
                             const float* __restrict__ Wv, const float* __restrict__ W1) {
    int t = blockIdx.x * blockDim.x + threadIdx.x;
    int stride = gridDim.x * blockDim.x;
    for (int i = t; i < 112 * 128; i += stride) {
        int kk = i >> 7, c = i & 127;
        g_WkT[i] = Wk[c * 112 + kk];
        g_WqT[i] = Wq[c * 112 + kk];
    }
    for (int i = t; i < 128 * 128; i += stride) {
        int f = i >> 7, c = i & 127;
        g_WvT[i] = Wv[c * 128 + f];
    }
    for (int i = t; i < 128 * 64; i += stride) {
        int d = i >> 6, h = i & 63;
        g_W1T[i] = W1[h * 128 + d];
    }
}

// Shared memory (floats), two aliased regions (same map as R6):
//  A @0 (5184):   phases 0-2: stT[112][36]@0, actT[16][36]@4032, polT[16][36]@4608
//                 phases 4-5: aw1[32][65]@0, adw1[32][65]@2080
//  B @5184 (9216): k/q then av: k_s[32][128]@5184, q_s[32][129]@9280
//                               avoT[128][36]@5184, avdT[128][36]@9792
//  sw1[32][64]@14400, wt[32][17]@16448, w2s[64]@16992
#define OFF_STT   0
#define OFF_ACTT  4032
#define OFF_POLT  4608
#define OFF_AW1   0
#define OFF_ADW1  2080
#define OFF_K     5184
#define OFF_Q     9280
#define OFF_AVO   5184
#define OFF_AVD   9792
#define OFF_SW1   14400
#define OFF_WT    16448
#define OFF_W2    16992
#define SMEM_FLOATS 17056
#define SMEM_BYTES  (SMEM_FLOATS * 4)

__global__ void __launch_bounds__(256, 3)
critic_kernel(const float* __restrict__ states,
              const float* __restrict__ policies,
              const float* __restrict__ actions,
              const float* __restrict__ bk,
              const float* __restrict__ bq,
              const float* __restrict__ bv,
              const float* __restrict__ W2,
              float* __restrict__ out,
              int out_size) {
    extern __shared__ float sm[];
    float* stT  = sm + OFF_STT;
    float* actT = sm + OFF_ACTT;
    float* polT = sm + OFF_POLT;
    float* aw1  = sm + OFF_AW1;
    float* adw1 = sm + OFF_ADW1;
    float* k_s  = sm + OFF_K;
    float* q_s  = sm + OFF_Q;
    float* avoT = sm + OFF_AVO;
    float* avdT = sm + OFF_AVD;
    float* sw1  = sm + OFF_SW1;
    float* wt   = sm + OFF_WT;
    float* w2s  = sm + OFF_W2;

    const int t = threadIdx.x;
    const int b0 = blockIdx.x * 2;

    // ---- phase 0: load inputs (transposed; rows packed bl*16+r) ----
    {
        const float* stb = states + b0 * (16 * 112);
        for (int idx = t; idx < 32 * 112; idx += 256) {
            int rg = idx / 112, kk = idx - rg * 112;
            stT[kk * 36 + rg] = stb[idx];
        }
#pragma unroll
        for (int s = 0; s < 2; s++) {
            int idx = t + 256 * s;
            int bl = idx >> 8, rem = idx & 255, i = rem >> 4, a = rem & 15;
            actT[a * 36 + bl * 16 + i] = actions[b0 * 256 + idx];
            polT[a * 36 + bl * 16 + i] = policies[b0 * 256 + idx];
        }
        if (t < 64) w2s[t] = W2[t];
    }
    __syncthreads();

    const int c = t & 127, bl = t >> 7;
    const int rbase = bl * 16;

    // ---- fused phase 1+2a: k, q, and av-states partial in ONE stT pass ----
    ULL sh[8];
    {
        ULL ka[8], qa[8];
        {
            float bkc = bk[c], bqc = bq[c], bvc = bv[c];
#pragma unroll
            for (int rp = 0; rp < 8; rp++) {
                PACK2(ka[rp], bkc, bkc);
                PACK2(qa[rp], bqc, bqc);
                PACK2(sh[rp], bvc, bvc);
            }
        }
#pragma unroll 4
        for (int kk = 0; kk < 112; kk++) {
            float wk = g_WkT[kk * 128 + c];
            float wq = g_WqT[kk * 128 + c];
            float wv = g_WvT[kk * 128 + c];
            ULL wk2, wq2, wv2;
            PACK2(wk2, wk, wk); PACK2(wq2, wq, wq); PACK2(wv2, wv, wv);
            const ulonglong2* sp = reinterpret_cast<const ulonglong2*>(stT + kk * 36 + rbase);
#pragma unroll
            for (int p4 = 0; p4 < 4; p4++) {
                ulonglong2 sv = sp[p4];
                FMA2(ka[2 * p4], wk2, sv.x); FMA2(ka[2 * p4 + 1], wk2, sv.y);
                FMA2(qa[2 * p4], wq2, sv.x); FMA2(qa[2 * p4 + 1], wq2, sv.y);
                FMA2(sh[2 * p4], wv2, sv.x); FMA2(sh[2 * p4 + 1], wv2, sv.y);
            }
        }
        const float s = 0.08838834764831845f;  // 1/sqrt(128)
#pragma unroll
        for (int rp = 0; rp < 8; rp++) {
            float lo, hi;
            UNPACK2(lo, hi, ka[rp]);
            k_s[(rbase + 2 * rp) * 128 + c] = lo;
            k_s[(rbase + 2 * rp + 1) * 128 + c] = hi;
            UNPACK2(lo, hi, qa[rp]);
            q_s[(rbase + 2 * rp) * 129 + c] = lo * s;
            q_s[(rbase + 2 * rp + 1) * 129 + c] = hi * s;
        }
    }
    __syncthreads();

    // ---- phase 3: scores + softmax over i (sh stays live in regs) ----
#pragma unroll
    for (int s = 0; s < 2; s++) {
        int id = t + 256 * s;
        int sbl = id >> 8, j = (id >> 4) & 15, i = id & 15;
        const float* qp = q_s + (sbl * 16 + i) * 129;
        const float* kp = k_s + (sbl * 16 + j) * 128;
        float s0 = 0.f, s1 = 0.f, s2 = 0.f, s3 = 0.f;
#pragma unroll 8
        for (int d = 0; d < 128; d += 4) {
            s0 = fmaf(qp[d + 0], kp[d + 0], s0);
            s1 = fmaf(qp[d + 1], kp[d + 1], s1);
            s2 = fmaf(qp[d + 2], kp[d + 2], s2);
            s3 = fmaf(qp[d + 3], kp[d + 3], s3);
        }
        float sc = (s0 + s1) + (s2 + s3);
        float m = sc;
#pragma unroll
        for (int o = 8; o; o >>= 1) m = fmaxf(m, __shfl_xor_sync(0xffffffffu, m, o));
        float e = __expf(sc - m);
        float sum = e;
#pragma unroll
        for (int o = 8; o; o >>= 1) sum += __shfl_xor_sync(0xffffffffu, sum, o);
        wt[(sbl * 16 + j) * 17 + i] = e / sum;
    }
    __syncthreads();

    // ---- phase 2b: act/pol tails -> avoff/avdiag (overwrite dead k/q) ----
    {
        // actions tail -> avoff
        {
            ULL wk_[8];
#pragma unroll
            for (int rp = 0; rp < 8; rp++) wk_[rp] = sh[rp];
#pragma unroll 4
            for (int f = 0; f < 16; f++) {
                float w = g_WvT[(112 + f) * 128 + c];
                ULL w2; PACK2(w2, w, w);
                const ulonglong2* sp = reinterpret_cast<const ulonglong2*>(actT + f * 36 + rbase);
#pragma unroll
                for (int p4 = 0; p4 < 4; p4++) {
                    ulonglong2 sv = sp[p4];
                    FMA2(wk_[2 * p4], w2, sv.x); FMA2(wk_[2 * p4 + 1], w2, sv.y);
                }
            }
            float v[16];
#pragma unroll
            for (int rp = 0; rp < 8; rp++) {
                float lo, hi; UNPACK2(lo, hi, wk_[rp]);
                TANHA(v[2 * rp], lo); TANHA(v[2 * rp + 1], hi);
            }
            float* dst = avoT + c * 36 + rbase;
#pragma unroll
            for (int p4 = 0; p4 < 4; p4++)
                *reinterpret_cast<float4*>(dst + 4 * p4) =
                    make_float4(v[4 * p4], v[4 * p4 + 1], v[4 * p4 + 2], v[4 * p4 + 3]);
        }
        // policies tail -> avdiag
        {
            ULL wk_[8];
#pragma unroll
            for (int rp = 0; rp < 8; rp++) wk_[rp] = sh[rp];
#pragma unroll 4
            for (int f = 0; f < 16; f++) {
                float w = g_WvT[(112 + f) * 128 + c];
                ULL w2; PACK2(w2, w, w);
                const ulonglong2* sp = reinterpret_cast<const ulonglong2*>(polT + f * 36 + rbase);
#pragma unroll
                for (int p4 = 0; p4 < 4; p4++) {
                    ulonglong2 sv = sp[p4];
                    FMA2(wk_[2 * p4], w2, sv.x); FMA2(wk_[2 * p4 + 1], w2, sv.y);
                }
            }
            float v[16];
#pragma unroll
            for (int rp = 0; rp < 8; rp++) {
                float lo, hi; UNPACK2(lo, hi, wk_[rp]);
                TANHA(v[2 * rp], lo); TANHA(v[2 * rp + 1], hi);
            }
            float* dst = avdT + c * 36 + rbase;
#pragma unroll
            for (int p4 = 0; p4 < 4; p4++)
                *reinterpret_cast<float4*>(dst + 4 * p4) =
                    make_float4(v[4 * p4], v[4 * p4 + 1], v[4 * p4 + 2], v[4 * p4 + 3]);
        }
    }
    __syncthreads();

    // ---- phase 4: AW1/AdW1, 2 h-columns x 8 rows per thread ----
    {
        const int h = t & 31, m = (t >> 5) & 1, qd = t >> 6;  // qd in 0..3
        const int r0 = qd * 8;
        const float* srcT = m ? avdT : avoT;
        float* dst = m ? adw1 : aw1;
        ULL a0[4] = {}, a1[4] = {};
#pragma unroll 4
        for (int d = 0; d < 128; d++) {
            float w0 = g_W1T[d * 64 + h];
            float w1 = g_W1T[d * 64 + h + 32];
            ULL w02, w12; PACK2(w02, w0, w0); PACK2(w12, w1, w1);
            const ulonglong2* sp = reinterpret_cast<const ulonglong2*>(srcT + d * 36 + r0);
            ulonglong2 sv0 = sp[0], sv1 = sp[1];
            FMA2(a0[0], w02, sv0.x); FMA2(a0[1], w02, sv0.y);
            FMA2(a0[2], w02, sv1.x); FMA2(a0[3], w02, sv1.y);
            FMA2(a1[0], w12, sv0.x); FMA2(a1[1], w12, sv0.y);
            FMA2(a1[2], w12, sv1.x); FMA2(a1[3], w12, sv1.y);
        }
#pragma unroll
        for (int rp = 0; rp < 4; rp++) {
            float lo, hi;
            UNPACK2(lo, hi, a0[rp]);
            dst[(r0 + 2 * rp) * 65 + h] = lo;
            dst[(r0 + 2 * rp + 1) * 65 + h] = hi;
            UNPACK2(lo, hi, a1[rp]);
            dst[(r0 + 2 * rp) * 65 + h + 32] = lo;
            dst[(r0 + 2 * rp + 1) * 65 + h + 32] = hi;
        }
    }
    __syncthreads();

    // ---- phase 5a: SW1[ag,h] = sum_i wt[ag,i] * AW1[bl*16+i,h] ----
    {
        int h = t & 63, g = t >> 6, a0 = g * 8;
        int blr = (a0 >> 4) * 16;
        float acc[8] = {};
#pragma unroll
        for (int i = 0; i < 16; i++) {
            float aw_ = aw1[(blr + i) * 65 + h];
#pragma unroll
            for (int aa = 0; aa < 8; aa++)
                acc[aa] = fmaf(wt[(a0 + aa) * 17 + i], aw_, acc[aa]);
        }
#pragma unroll
        for (int aa = 0; aa < 8; aa++) sw1[(a0 + aa) * 64 + h] = acc[aa];
    }
    __syncthreads();

    // ---- phase 5b: value + weight outputs ----
    {
        int a = t >> 4, j = t & 15;
#pragma unroll
        for (int sbl = 0; sbl < 2; sbl++) {
            int ag = sbl * 16 + a, jg = sbl * 16 + j;
            float waj = wt[ag * 17 + j];
            float acc = 0.f;
#pragma unroll 8
            for (int h = 0; h < 64; h++) {
                float dd = adw1[jg * 65 + h] - aw1[jg * 65 + h];
                float nf = (sw1[ag * 64 + h] + dd * waj) * 0.0625f;
                float v = nf > 0.f ? nf : 0.01f * nf;
                acc = fmaf(v, w2s[h], acc);
            }
            out[(b0 + sbl) * 256 + t] = acc;                  // value[b, a, j, 0]
            if (out_size >= 262144)                            // weight[b, j, i]
                out[131072 + (b0 + sbl) * 256 + t] = wt[(sbl * 16 + (t >> 4)) * 17 + (t & 15)];
        }
    }
}

extern "C" void kernel_launch(void* const* d_in, const int* in_sizes, int n_in,
                              void* d_out, int out_size) {
    const float* states   = (const float*)d_in[0];
    const float* policies = (const float*)d_in[1];
    const float* actions  = (const float*)d_in[2];
    const float* Wk       = (const float*)d_in[3];
    const float* bk       = (const float*)d_in[4];
    const float* Wq       = (const float*)d_in[5];
    const float* bq       = (const float*)d_in[6];
    const float* Wv       = (const float*)d_in[7];
    const float* bv       = (const float*)d_in[8];
    const float* W1       = (const float*)d_in[9];
    const float* W2       = (const float*)d_in[10];
    float* out = (float*)d_out;

    cudaFuncSetAttribute(critic_kernel, cudaFuncAttributeMaxDynamicSharedMemorySize, SMEM_BYTES);

    prep_weights<<<48, 256>>>(Wk, Wq, Wv, W1);
    critic_kernel<<<256, 256, SMEM_BYTES>>>(states, policies, actions,
                                            bk, bq, bv, W2, out, out_size);
}

// round 8
// speedup vs baseline: 1.0843x; 1.0843x over previous
#include <cuda_runtime.h>

// ---------------------------------------------------------------------------
// ScalarDotProductCriticNetworkV8 — fused kernel, 2 batches per CTA (R8).
//
// Shapes: B=512, N=16, A=16, OBS=112, D=128, H=64, F_IN=128. Grid=256, NB=2.
//
// R8 = R6 structure (R7's P1+P2 fusion reverted: it thrashed L1D with 3
// weight streams, L2% 1->9.8) + scalar-LDS elimination:
//  * q_s row stride 129 -> 132: P3 reads q via float4 (was 128 scalar LDS)
//  * aw1/adw1 row stride 65 -> 68: P5b reads via float4 (was 384 scalar LDS)
// L1 wavefronts/thread ~2100 -> ~1620.
// ---------------------------------------------------------------------------

#define ULL unsigned long long

#define PACK2(d, lo, hi) asm("mov.b64 %0, {%1, %2};" : "=l"(d) : "f"(lo), "f"(hi))
#define UNPACK2(lo, hi, v) asm("mov.b64 {%0, %1}, %2;" : "=f"(lo), "=f"(hi) : "l"(v))
#define FMA2(acc, a, b) asm("fma.rn.f32x2 %0, %1, %2, %0;" : "+l"(acc) : "l"(a), "l"(b))
#define TANHA(y, x) asm("tanh.approx.f32 %0, %1;" : "=f"(y) : "f"(x))

// Pre-transposed weights (scratch; filled by prep kernel each launch).
__device__ float g_WkT[112 * 128];   // [kk][c]
__device__ float g_WqT[112 * 128];   // [kk][c]
__device__ float g_WvT[128 * 128];   // [f][c]
__device__ float g_W1T[128 * 64];    // [d][h]

__global__ void prep_weights(const float* __restrict__ Wk, const float* __restrict__ Wq,
                             const float* __restrict__ Wv, const float* __restrict__ W1) {
    int t = blockIdx.x * blockDim.x + threadIdx.x;
    int stride = gridDim.x * blockDim.x;
    for (int i = t; i < 112 * 128; i += stride) {
        int kk = i >> 7, c = i & 127;
        g_WkT[i] = Wk[c * 112 + kk];
        g_WqT[i] = Wq[c * 112 + kk];
    }
    for (int i = t; i < 128 * 128; i += stride) {
        int f = i >> 7, c = i & 127;
        g_WvT[i] = Wv[c * 128 + f];
    }
    for (int i = t; i < 128 * 64; i += stride) {
        int d = i >> 6, h = i & 63;
        g_W1T[i] = W1[h * 128 + d];
    }
}

// Shared memory (floats), two aliased regions:
//  A @0 (5184):   phases 0-2: stT[112][36]@0, actT[16][36]@4032, polT[16][36]@4608
//                 phases 4-5: aw1[32][68]@0, adw1[32][68]@2176  (ends 4352)
//  B @5184 (9216): phases 1,3: k_s[32][128]@5184, q_s[32][132]@9280 (ends 13504)
//                  phases 2,4: avoT[128][36]@5184, avdT[128][36]@9792
//  sw1[32][64]@14400, wt[32][17]@16448, w2s[64]@16992
#define OFF_STT   0
#define OFF_ACTT  4032
#define OFF_POLT  4608
#define OFF_AW1   0
#define OFF_ADW1  2176
#define OFF_K     5184
#define OFF_Q     9280
#define OFF_AVO   5184
#define OFF_AVD   9792
#define OFF_SW1   14400
#define OFF_WT    16448
#define OFF_W2    16992
#define SMEM_FLOATS 17056
#define SMEM_BYTES  (SMEM_FLOATS * 4)

__global__ void __launch_bounds__(256, 2)
critic_kernel(const float* __restrict__ states,
              const float* __restrict__ policies,
              const float* __restrict__ actions,
              const float* __restrict__ bk,
              const float* __restrict__ bq,
              const float* __restrict__ bv,
              const float* __restrict__ W2,
              float* __restrict__ out,
              int out_size) {
    extern __shared__ float sm[];
    float* stT  = sm + OFF_STT;
    float* actT = sm + OFF_ACTT;
    float* polT = sm + OFF_POLT;
    float* aw1  = sm + OFF_AW1;
    float* adw1 = sm + OFF_ADW1;
    float* k_s  = sm + OFF_K;
    float* q_s  = sm + OFF_Q;
    float* avoT = sm + OFF_AVO;
    float* avdT = sm + OFF_AVD;
    float* sw1  = sm + OFF_SW1;
    float* wt   = sm + OFF_WT;
    float* w2s  = sm + OFF_W2;

    const int t = threadIdx.x;
    const int b0 = blockIdx.x * 2;

    // ---- phase 0: load inputs (transposed; rows packed bl*16+r) ----
    {
        const float* stb = states + b0 * (16 * 112);
        for (int idx = t; idx < 32 * 112; idx += 256) {
            int rg = idx / 112, kk = idx - rg * 112;
            stT[kk * 36 + rg] = stb[idx];
        }
#pragma unroll
        for (int s = 0; s < 2; s++) {
            int idx = t + 256 * s;
            int bl = idx >> 8, rem = idx & 255, i = rem >> 4, a = rem & 15;
            actT[a * 36 + bl * 16 + i] = actions[b0 * 256 + idx];
            polT[a * 36 + bl * 16 + i] = policies[b0 * 256 + idx];
        }
        if (t < 64) w2s[t] = W2[t];
    }
    __syncthreads();

    // ---- phase 1: k AND q for 16 rows per thread (c = col, bl = batch) ----
    {
        const int c = t & 127, bl = t >> 7;
        const int rbase = bl * 16;
        ULL ka[8], qa[8];
        {
            float bkc = bk[c], bqc = bq[c];
#pragma unroll
            for (int rp = 0; rp < 8; rp++) { PACK2(ka[rp], bkc, bkc); PACK2(qa[rp], bqc, bqc); }
        }
#pragma unroll 4
        for (int kk = 0; kk < 112; kk++) {
            float wk = g_WkT[kk * 128 + c];
            float wq = g_WqT[kk * 128 + c];
            ULL wk2, wq2; PACK2(wk2, wk, wk); PACK2(wq2, wq, wq);
            const ulonglong2* sp = reinterpret_cast<const ulonglong2*>(stT + kk * 36 + rbase);
#pragma unroll
            for (int p4 = 0; p4 < 4; p4++) {
                ulonglong2 sv = sp[p4];
                FMA2(ka[2 * p4], wk2, sv.x); FMA2(ka[2 * p4 + 1], wk2, sv.y);
                FMA2(qa[2 * p4], wq2, sv.x); FMA2(qa[2 * p4 + 1], wq2, sv.y);
            }
        }
        const float s = 0.08838834764831845f;  // 1/sqrt(128)
#pragma unroll
        for (int rp = 0; rp < 8; rp++) {
            float lo, hi;
            UNPACK2(lo, hi, ka[rp]);
            k_s[(rbase + 2 * rp) * 128 + c] = lo;
            k_s[(rbase + 2 * rp + 1) * 128 + c] = hi;
            UNPACK2(lo, hi, qa[rp]);
            q_s[(rbase + 2 * rp) * 132 + c] = lo * s;
            q_s[(rbase + 2 * rp + 1) * 132 + c] = hi * s;
        }
    }
    __syncthreads();

    // ---- phase 3: scores + softmax over i (float4 LDS for q and k) ----
#pragma unroll
    for (int s = 0; s < 2; s++) {
        int id = t + 256 * s;
        int sbl = id >> 8, j = (id >> 4) & 15, i = id & 15;
        const float4* qp = reinterpret_cast<const float4*>(q_s + (sbl * 16 + i) * 132);
        const float4* kp = reinterpret_cast<const float4*>(k_s + (sbl * 16 + j) * 128);
        float s0 = 0.f, s1 = 0.f, s2 = 0.f, s3 = 0.f;
#pragma unroll 8
        for (int d4 = 0; d4 < 32; d4++) {
            float4 qv = qp[d4];
            float4 kv = kp[d4];
            s0 = fmaf(qv.x, kv.x, s0);
            s1 = fmaf(qv.y, kv.y, s1);
            s2 = fmaf(qv.z, kv.z, s2);
            s3 = fmaf(qv.w, kv.w, s3);
        }
        float sc = (s0 + s1) + (s2 + s3);
        float m = sc;
#pragma unroll
        for (int o = 8; o; o >>= 1) m = fmaxf(m, __shfl_xor_sync(0xffffffffu, m, o));
        float e = __expf(sc - m);
        float sum = e;
#pragma unroll
        for (int o = 8; o; o >>= 1) sum += __shfl_xor_sync(0xffffffffu, sum, o);
        wt[(sbl * 16 + j) * 17 + i] = e / sum;
    }
    __syncthreads();

    // ---- phase 2: avoff/avdiag with shared states partial (16 rows/thread) ----
    // (avoT/avdT overwrite dead k_s/q_s)
    {
        const int c = t & 127, bl = t >> 7;
        const int rbase = bl * 16;
        ULL sh[8];
        {
            float bvc = bv[c];
#pragma unroll
            for (int rp = 0; rp < 8; rp++) PACK2(sh[rp], bvc, bvc);
        }
#pragma unroll 4
        for (int f = 0; f < 112; f++) {
            float w = g_WvT[f * 128 + c];
            ULL w2; PACK2(w2, w, w);
            const ulonglong2* sp = reinterpret_cast<const ulonglong2*>(stT + f * 36 + rbase);
#pragma unroll
            for (int p4 = 0; p4 < 4; p4++) {
                ulonglong2 sv = sp[p4];
                FMA2(sh[2 * p4], w2, sv.x); FMA2(sh[2 * p4 + 1], w2, sv.y);
            }
        }
        // actions tail -> avoff
        {
            ULL wk_[8];
#pragma unroll
            for (int rp = 0; rp < 8; rp++) wk_[rp] = sh[rp];
#pragma unroll 4
            for (int f = 0; f < 16; f++) {
                float w = g_WvT[(112 + f) * 128 + c];
                ULL w2; PACK2(w2, w, w);
                const ulonglong2* sp = reinterpret_cast<const ulonglong2*>(actT + f * 36 + rbase);
#pragma unroll
                for (int p4 = 0; p4 < 4; p4++) {
                    ulonglong2 sv = sp[p4];
                    FMA2(wk_[2 * p4], w2, sv.x); FMA2(wk_[2 * p4 + 1], w2, sv.y);
                }
            }
            float v[16];
#pragma unroll
            for (int rp = 0; rp < 8; rp++) {
                float lo, hi; UNPACK2(lo, hi, wk_[rp]);
                TANHA(v[2 * rp], lo); TANHA(v[2 * rp + 1], hi);
            }
            float* dst = avoT + c * 36 + rbase;
#pragma unroll
            for (int p4 = 0; p4 < 4; p4++)
                *reinterpret_cast<float4*>(dst + 4 * p4) =
                    make_float4(v[4 * p4], v[4 * p4 + 1], v[4 * p4 + 2], v[4 * p4 + 3]);
        }
        // policies tail -> avdiag
        {
            ULL wk_[8];
#pragma unroll
            for (int rp = 0; rp < 8; rp++) wk_[rp] = sh[rp];
#pragma unroll 4
            for (int f = 0; f < 16; f++) {
                float w = g_WvT[(112 + f) * 128 + c];
                ULL w2; PACK2(w2, w, w);
                const ulonglong2* sp = reinterpret_cast<const ulonglong2*>(polT + f * 36 + rbase);
#pragma unroll
                for (int p4 = 0; p4 < 4; p4++) {
                    ulonglong2 sv = sp[p4];
                    FMA2(wk_[2 * p4], w2, sv.x); FMA2(wk_[2 * p4 + 1], w2, sv.y);
                }
            }
            float v[16];
#pragma unroll
            for (int rp = 0; rp < 8; rp++) {
                float lo, hi; UNPACK2(lo, hi, wk_[rp]);
                TANHA(v[2 * rp], lo); TANHA(v[2 * rp + 1], hi);
            }
            float* dst = avdT + c * 36 + rbase;
#pragma unroll
            for (int p4 = 0; p4 < 4; p4++)
                *reinterpret_cast<float4*>(dst + 4 * p4) =
                    make_float4(v[4 * p4], v[4 * p4 + 1], v[4 * p4 + 2], v[4 * p4 + 3]);
        }
    }
    __syncthreads();

    // ---- phase 4: AW1/AdW1, 2 h-columns x 8 rows per thread ----
    // (aw1/adw1 overwrite dead stT/actT/polT)
    {
        const int h = t & 31, m = (t >> 5) & 1, qd = t >> 6;  // qd in 0..3
        const int r0 = qd * 8;
        const float* srcT = m ? avdT : avoT;
        float* dst = m ? adw1 : aw1;
        ULL a0[4] = {}, a1[4] = {};
#pragma unroll 4
        for (int d = 0; d < 128; d++) {
            float w0 = g_W1T[d * 64 + h];
            float w1 = g_W1T[d * 64 + h + 32];
            ULL w02, w12; PACK2(w02, w0, w0); PACK2(w12, w1, w1);
            const ulonglong2* sp = reinterpret_cast<const ulonglong2*>(srcT + d * 36 + r0);
            ulonglong2 sv0 = sp[0], sv1 = sp[1];
            FMA2(a0[0], w02, sv0.x); FMA2(a0[1], w02, sv0.y);
            FMA2(a0[2], w02, sv1.x); FMA2(a0[3], w02, sv1.y);
            FMA2(a1[0], w12, sv0.x); FMA2(a1[1], w12, sv0.y);
            FMA2(a1[2], w12, sv1.x); FMA2(a1[3], w12, sv1.y);
        }
#pragma unroll
        for (int rp = 0; rp < 4; rp++) {
            float lo, hi;
            UNPACK2(lo, hi, a0[rp]);
            dst[(r0 + 2 * rp) * 68 + h] = lo;
            dst[(r0 + 2 * rp + 1) * 68 + h] = hi;
            UNPACK2(lo, hi, a1[rp]);
            dst[(r0 + 2 * rp) * 68 + h + 32] = lo;
            dst[(r0 + 2 * rp + 1) * 68 + h + 32] = hi;
        }
    }
    __syncthreads();

    // ---- phase 5a: SW1[ag,h] = sum_i wt[ag,i] * AW1[bl*16+i,h] ----
    {
        int h = t & 63, g = t >> 6, a0 = g * 8;
        int blr = (a0 >> 4) * 16;
        float acc[8] = {};
#pragma unroll
        for (int i = 0; i < 16; i++) {
            float aw_ = aw1[(blr + i) * 68 + h];
#pragma unroll
            for (int aa = 0; aa < 8; aa++)
                acc[aa] = fmaf(wt[(a0 + aa) * 17 + i], aw_, acc[aa]);
        }
#pragma unroll
        for (int aa = 0; aa < 8; aa++) sw1[(a0 + aa) * 64 + h] = acc[aa];
    }
    __syncthreads();

    // ---- phase 5b: value + weight outputs (float4 LDS) ----
    {
        int a = t >> 4, j = t & 15;
#pragma unroll
        for (int sbl = 0; sbl < 2; sbl++) {
            int ag = sbl * 16 + a, jg = sbl * 16 + j;
            float waj = wt[ag * 17 + j];
            const float4* adp = reinterpret_cast<const float4*>(adw1 + jg * 68);
            const float4* awp = reinterpret_cast<const float4*>(aw1 + jg * 68);
            const float4* swp = reinterpret_cast<const float4*>(sw1 + ag * 64);
            const float4* w2p = reinterpret_cast<const float4*>(w2s);
            float acc = 0.f;
#pragma unroll
            for (int h4 = 0; h4 < 16; h4++) {
                float4 ad = adp[h4], aw = awp[h4], swv = swp[h4], w2 = w2p[h4];
                float nf, v;
                nf = (swv.x + (ad.x - aw.x) * waj) * 0.0625f;
                v = nf > 0.f ? nf : 0.01f * nf; acc = fmaf(v, w2.x, acc);
                nf = (swv.y + (ad.y - aw.y) * waj) * 0.0625f;
                v = nf > 0.f ? nf : 0.01f * nf; acc = fmaf(v, w2.y, acc);
                nf = (swv.z + (ad.z - aw.z) * waj) * 0.0625f;
                v = nf > 0.f ? nf : 0.01f * nf; acc = fmaf(v, w2.z, acc);
                nf = (swv.w + (ad.w - aw.w) * waj) * 0.0625f;
                v = nf > 0.f ? nf : 0.01f * nf; acc = fmaf(v, w2.w, acc);
            }
            out[(b0 + sbl) * 256 + t] = acc;                  // value[b, a, j, 0]
            if (out_size >= 262144)                            // weight[b, j, i]
                out[131072 + (b0 + sbl) * 256 + t] = wt[(sbl * 16 + (t >> 4)) * 17 + (t & 15)];
        }
    }
}

extern "C" void kernel_launch(void* const* d_in, const int* in_sizes, int n_in,
                              void* d_out, int out_size) {
    const float* states   = (const float*)d_in[0];
    const float* policies = (const float*)d_in[1];
    const float* actions  = (const float*)d_in[2];
    const float* Wk       = (const float*)d_in[3];
    const float* bk       = (const float*)d_in[4];
    const float* Wq       = (const float*)d_in[5];
    const float* bq       = (const float*)d_in[6];
    const float* Wv       = (const float*)d_in[7];
    const float* bv       = (const float*)d_in[8];
    const float* W1       = (const float*)d_in[9];
    const float* W2       = (const float*)d_in[10];
    float* out = (float*)d_out;

    cudaFuncSetAttribute(critic_kernel, cudaFuncAttributeMaxDynamicSharedMemorySize, SMEM_BYTES);

    prep_weights<<<48, 256>>>(Wk, Wq, Wv, W1);
    critic_kernel<<<256, 256, SMEM_BYTES>>>(states, policies, actions,
                                            bk, bq, bv, W2, out, out_size);
}